// round 1
// baseline (speedup 1.0000x reference)
#include <cuda_runtime.h>

// FDTD wave cell, fused pointwise + 5-point Laplacian.
// Shapes: h1,h2,c_linear,rho: [8,1024,1024] f32; b_geom: [1024,1024] f32.
// Output: concat(y, h1) -> 2*8*1024*1024 f32.
//
// Constants: DT=0.5 -> dt^-2=4, 2/dt^2=8, dt^-1=2 ; H=1 ; b0=1 ; uth=1 ; c_nl=0.01

#define NX 1024
#define NY 1024
#define NB 8
#define NX4 (NX / 4)          // 256 float4 chunks per row
#define PLANE (NY * NX)       // 1M elements per batch image

__global__ __launch_bounds__(256)
void wavecell_kernel(const float* __restrict__ h1,
                     const float* __restrict__ h2,
                     const float* __restrict__ c_linear,
                     const float* __restrict__ rho,
                     const float* __restrict__ b_geom,
                     float* __restrict__ out)
{
    // Thread mapping: x4 fastest, batch middle, y slowest.
    // blockDim = 256 => one block == one full row (1024 floats) of one batch image.
    const int t   = blockIdx.x * blockDim.x + threadIdx.x;
    const int x4  = t & (NX4 - 1);          // 0..255
    const int b   = (t >> 8) & (NB - 1);    // 0..7
    const int y   = t >> 11;                // 0..1023
    if (y >= NY) return;

    const int x0   = x4 * 4;                       // first x of this chunk
    const long base = (long)b * PLANE + (long)y * NX + x0;

    // Vector loads (all 16B aligned)
    const float4 v1 = *(const float4*)(h1 + base);
    const float4 v2 = *(const float4*)(h2 + base);
    const float4 vc = *(const float4*)(c_linear + base);
    const float4 vr = *(const float4*)(rho + base);
    const float4 vb = *(const float4*)(b_geom + (long)y * NX + x0);

    // Vertical neighbors (zero padding at y=0 / y=NY-1)
    float4 up   = make_float4(0.f, 0.f, 0.f, 0.f);
    float4 down = make_float4(0.f, 0.f, 0.f, 0.f);
    if (y > 0)      up   = *(const float4*)(h1 + base - NX);
    if (y < NY - 1) down = *(const float4*)(h1 + base + NX);

    // Horizontal neighbors: scalar edge loads (L1 hits), zero at x boundaries
    const float left  = (x0 > 0)          ? h1[base - 1] : 0.f;
    const float right = (x0 + 4 < NX)     ? h1[base + 4] : 0.f;

    float c1[4] = {v1.x, v1.y, v1.z, v1.w};
    float c2[4] = {v2.x, v2.y, v2.z, v2.w};
    float cl[4] = {vc.x, vc.y, vc.z, vc.w};
    float rh[4] = {vr.x, vr.y, vr.z, vr.w};
    float bg[4] = {vb.x, vb.y, vb.z, vb.w};
    float u4[4] = {up.x, up.y, up.z, up.w};
    float d4[4] = {down.x, down.y, down.z, down.w};

    float lft[4] = {left,  c1[0], c1[1], c1[2]};
    float rgt[4] = {c1[1], c1[2], c1[3], right};

    float yv[4];
#pragma unroll
    for (int i = 0; i < 4; i++) {
        const float hh  = c1[i];
        const float hh2 = hh * hh;
        // b = b_geom + rho / (1 + h1^2)
        const float bv = bg[i] + rh[i] * __frcp_rn(1.0f + hh2);
        // c = c_linear + 0.01 * rho * h1^2
        const float cv = cl[i] + 0.01f * rh[i] * hh2;
        // laplacian (h=1)
        const float lap = u4[i] + d4[i] + lft[i] + rgt[i] - 4.0f * hh;
        // inv = 1 / (4 + 2b);  y = inv*(8*h1 - (4 - 2b)*h2 + c^2*lap)
        const float inv = __frcp_rn(4.0f + 2.0f * bv);
        yv[i] = inv * (8.0f * hh - (4.0f - 2.0f * bv) * c2[i] + cv * cv * lap);
    }

    float4 vy = make_float4(yv[0], yv[1], yv[2], yv[3]);
    *(float4*)(out + base) = vy;
    // second output: copy of h1
    *(float4*)(out + (long)NB * PLANE + base) = v1;
}

extern "C" void kernel_launch(void* const* d_in, const int* in_sizes, int n_in,
                              void* d_out, int out_size)
{
    const float* h1       = (const float*)d_in[0];
    const float* h2       = (const float*)d_in[1];
    const float* c_linear = (const float*)d_in[2];
    const float* rho      = (const float*)d_in[3];
    const float* b_geom   = (const float*)d_in[4];
    float* out            = (float*)d_out;

    const int total_chunks = NB * NY * NX4;   // 2,097,152 threads
    const int block = 256;
    const int grid  = total_chunks / block;   // 8192 blocks
    wavecell_kernel<<<grid, block>>>(h1, h2, c_linear, rho, b_geom, out);
}

// round 2
// speedup vs baseline: 1.0203x; 1.0203x over previous
#include <cuda_runtime.h>

// FDTD wave cell, fused pointwise + 5-point Laplacian. 8 floats per thread.
// Shapes: h1,h2,c_linear,rho: [8,1024,1024] f32; b_geom: [1024,1024] f32.
// Output: concat(y, h1) -> 2*8*1024*1024 f32.
// Constants: DT=0.5 -> dt^-2=4, 2/dt^2=8, dt^-1=2 ; H=1 ; b0=1 ; uth=1 ; c_nl=0.01

#define NX 1024
#define NY 1024
#define NB 8
#define NX8 (NX / 8)          // 128 8-float chunks per row
#define PLANE (NY * NX)       // 1M elements per batch image

__global__ __launch_bounds__(256)
void wavecell_kernel(const float* __restrict__ h1,
                     const float* __restrict__ h2,
                     const float* __restrict__ c_linear,
                     const float* __restrict__ rho,
                     const float* __restrict__ b_geom,
                     float* __restrict__ out)
{
    // Mapping: x8 fastest, batch middle, y slowest (adjacent blocks share rows
    // across batch -> b_geom + vertical-neighbor rows stay L2-resident).
    const int t  = blockIdx.x * blockDim.x + threadIdx.x;
    const int x8 = t & (NX8 - 1);           // 0..127
    const int b  = (t >> 7) & (NB - 1);     // 0..7
    const int y  = t >> 10;                 // 0..1023

    const int x0    = x8 * 8;
    const long base = (long)b * PLANE + (long)y * NX + x0;
    const long gbase = (long)y * NX + x0;

    // ---- Front-batched loads (maximize MLP) ----
    // h1 center: default caching (neighbors reuse via L1/L2)
    const float4 v1a = *(const float4*)(h1 + base);
    const float4 v1b = *(const float4*)(h1 + base + 4);

    // Vertical neighbors (zero padding at y boundaries)
    float4 upa = make_float4(0.f,0.f,0.f,0.f), upb = upa;
    float4 dna = upa, dnb = upa;
    if (y > 0) {
        upa = *(const float4*)(h1 + base - NX);
        upb = *(const float4*)(h1 + base - NX + 4);
    }
    if (y < NY - 1) {
        dna = *(const float4*)(h1 + base + NX);
        dnb = *(const float4*)(h1 + base + NX + 4);
    }

    // Use-once operands: streaming (evict-first), keep L2 for h1/b_geom
    const float4 v2a = __ldcs((const float4*)(h2 + base));
    const float4 v2b = __ldcs((const float4*)(h2 + base + 4));
    const float4 vca = __ldcs((const float4*)(c_linear + base));
    const float4 vcb = __ldcs((const float4*)(c_linear + base + 4));
    const float4 vra = __ldcs((const float4*)(rho + base));
    const float4 vrb = __ldcs((const float4*)(rho + base + 4));

    // b_geom: reused 8x across batch -> default caching
    const float4 vba = *(const float4*)(b_geom + gbase);
    const float4 vbb = *(const float4*)(b_geom + gbase + 4);

    // Horizontal edge neighbors (L1 hits; zero at x boundaries)
    const float left  = (x0 > 0)       ? h1[base - 1] : 0.f;
    const float right = (x0 + 8 < NX)  ? h1[base + 8] : 0.f;

    float c1[8] = {v1a.x,v1a.y,v1a.z,v1a.w, v1b.x,v1b.y,v1b.z,v1b.w};
    float c2[8] = {v2a.x,v2a.y,v2a.z,v2a.w, v2b.x,v2b.y,v2b.z,v2b.w};
    float cl[8] = {vca.x,vca.y,vca.z,vca.w, vcb.x,vcb.y,vcb.z,vcb.w};
    float rh[8] = {vra.x,vra.y,vra.z,vra.w, vrb.x,vrb.y,vrb.z,vrb.w};
    float bg[8] = {vba.x,vba.y,vba.z,vba.w, vbb.x,vbb.y,vbb.z,vbb.w};
    float uu[8] = {upa.x,upa.y,upa.z,upa.w, upb.x,upb.y,upb.z,upb.w};
    float dd[8] = {dna.x,dna.y,dna.z,dna.w, dnb.x,dnb.y,dnb.z,dnb.w};

    float yv[8];
#pragma unroll
    for (int i = 0; i < 8; i++) {
        const float hh  = c1[i];
        const float hh2 = hh * hh;
        const float lf  = (i == 0) ? left  : c1[i - 1];
        const float rt  = (i == 7) ? right : c1[i + 1];
        // b = b_geom + rho / (1 + h1^2)
        const float bv = bg[i] + rh[i] * __frcp_rn(1.0f + hh2);
        // c = c_linear + 0.01 * rho * h1^2
        const float cv = cl[i] + 0.01f * rh[i] * hh2;
        // laplacian (h=1)
        const float lap = uu[i] + dd[i] + lf + rt - 4.0f * hh;
        // inv = 1 / (4 + 2b);  y = inv*(8*h1 - (4 - 2b)*h2 + c^2*lap)
        const float inv = __frcp_rn(4.0f + 2.0f * bv);
        yv[i] = inv * (8.0f * hh - (4.0f - 2.0f * bv) * c2[i] + cv * cv * lap);
    }

    // Streaming stores (write-once, no reuse)
    __stcs((float4*)(out + base),     make_float4(yv[0], yv[1], yv[2], yv[3]));
    __stcs((float4*)(out + base + 4), make_float4(yv[4], yv[5], yv[6], yv[7]));
    __stcs((float4*)(out + (long)NB * PLANE + base),     v1a);
    __stcs((float4*)(out + (long)NB * PLANE + base + 4), v1b);
}

extern "C" void kernel_launch(void* const* d_in, const int* in_sizes, int n_in,
                              void* d_out, int out_size)
{
    const float* h1       = (const float*)d_in[0];
    const float* h2       = (const float*)d_in[1];
    const float* c_linear = (const float*)d_in[2];
    const float* rho      = (const float*)d_in[3];
    const float* b_geom   = (const float*)d_in[4];
    float* out            = (float*)d_out;

    const int total_chunks = NB * NY * NX8;   // 1,048,576 threads
    const int block = 256;
    const int grid  = total_chunks / block;   // 4096 blocks
    wavecell_kernel<<<grid, block>>>(h1, h2, c_linear, rho, b_geom, out);
}

// round 3
// speedup vs baseline: 1.1311x; 1.1086x over previous
#include <cuda_runtime.h>

// FDTD wave cell, fused pointwise + 5-point Laplacian. float4 per thread
// (R1 shape: 48 regs, occ ~52%) + streaming cache hints for use-once operands.
// Shapes: h1,h2,c_linear,rho: [8,1024,1024] f32; b_geom: [1024,1024] f32.
// Output: concat(y, h1) -> 2*8*1024*1024 f32.
// Constants: DT=0.5 -> dt^-2=4, 2/dt^2=8, dt^-1=2 ; H=1 ; b0=1 ; uth=1 ; c_nl=0.01

#define NX 1024
#define NY 1024
#define NB 8
#define NX4 (NX / 4)          // 256 float4 chunks per row
#define PLANE (NY * NX)       // 1M elements per batch image

__global__ __launch_bounds__(256)
void wavecell_kernel(const float* __restrict__ h1,
                     const float* __restrict__ h2,
                     const float* __restrict__ c_linear,
                     const float* __restrict__ rho,
                     const float* __restrict__ b_geom,
                     float* __restrict__ out)
{
    // Mapping: x4 fastest, batch middle, y slowest (adjacent blocks share rows
    // across batch -> b_geom + vertical-neighbor rows stay L2-resident).
    const int t   = blockIdx.x * blockDim.x + threadIdx.x;
    const int x4  = t & (NX4 - 1);          // 0..255
    const int b   = (t >> 8) & (NB - 1);    // 0..7
    const int y   = t >> 11;                // 0..1023

    const int x0    = x4 * 4;
    const long base = (long)b * PLANE + (long)y * NX + x0;

    // h1 center: default caching (horizontal/vertical neighbors reuse it)
    const float4 v1 = *(const float4*)(h1 + base);

    // Vertical neighbors (zero padding at y boundaries)
    float4 up   = make_float4(0.f, 0.f, 0.f, 0.f);
    float4 down = make_float4(0.f, 0.f, 0.f, 0.f);
    if (y > 0)      up   = *(const float4*)(h1 + base - NX);
    if (y < NY - 1) down = *(const float4*)(h1 + base + NX);

    // Use-once operands: streaming loads (evict-first), keep L2 for h1/b_geom
    const float4 v2 = __ldcs((const float4*)(h2 + base));
    const float4 vc = __ldcs((const float4*)(c_linear + base));
    const float4 vr = __ldcs((const float4*)(rho + base));

    // b_geom: reused 8x across batch -> default caching
    const float4 vb = *(const float4*)(b_geom + (long)y * NX + x0);

    // Horizontal edge neighbors (L1 hits; zero at x boundaries)
    const float left  = (x0 > 0)      ? h1[base - 1] : 0.f;
    const float right = (x0 + 4 < NX) ? h1[base + 4] : 0.f;

    float c1[4] = {v1.x, v1.y, v1.z, v1.w};
    float c2[4] = {v2.x, v2.y, v2.z, v2.w};
    float cl[4] = {vc.x, vc.y, vc.z, vc.w};
    float rh[4] = {vr.x, vr.y, vr.z, vr.w};
    float bg[4] = {vb.x, vb.y, vb.z, vb.w};
    float u4[4] = {up.x, up.y, up.z, up.w};
    float d4[4] = {down.x, down.y, down.z, down.w};

    float lft[4] = {left,  c1[0], c1[1], c1[2]};
    float rgt[4] = {c1[1], c1[2], c1[3], right};

    float yv[4];
#pragma unroll
    for (int i = 0; i < 4; i++) {
        const float hh  = c1[i];
        const float hh2 = hh * hh;
        // b = b_geom + rho / (1 + h1^2)
        const float bv = bg[i] + rh[i] * __frcp_rn(1.0f + hh2);
        // c = c_linear + 0.01 * rho * h1^2
        const float cv = cl[i] + 0.01f * rh[i] * hh2;
        // laplacian (h=1)
        const float lap = u4[i] + d4[i] + lft[i] + rgt[i] - 4.0f * hh;
        // inv = 1 / (4 + 2b);  y = inv*(8*h1 - (4 - 2b)*h2 + c^2*lap)
        const float inv = __frcp_rn(4.0f + 2.0f * bv);
        yv[i] = inv * (8.0f * hh - (4.0f - 2.0f * bv) * c2[i] + cv * cv * lap);
    }

    // Streaming stores (write-once, no reuse)
    __stcs((float4*)(out + base), make_float4(yv[0], yv[1], yv[2], yv[3]));
    __stcs((float4*)(out + (long)NB * PLANE + base), v1);
}

extern "C" void kernel_launch(void* const* d_in, const int* in_sizes, int n_in,
                              void* d_out, int out_size)
{
    const float* h1       = (const float*)d_in[0];
    const float* h2       = (const float*)d_in[1];
    const float* c_linear = (const float*)d_in[2];
    const float* rho      = (const float*)d_in[3];
    const float* b_geom   = (const float*)d_in[4];
    float* out            = (float*)d_out;

    const int total_chunks = NB * NY * NX4;   // 2,097,152 threads
    const int block = 256;
    const int grid  = total_chunks / block;   // 8192 blocks
    wavecell_kernel<<<grid, block>>>(h1, h2, c_linear, rho, b_geom, out);
}